// round 1
// baseline (speedup 1.0000x reference)
#include <cuda_runtime.h>
#include <math.h>

#define BATCH 4
#define NPTS  4096
#define KNN   16
#define NB    32          // 2*k neighbors per point
#define NPIX  (BATCH*NPTS*NB)

// ---------------- device scratch (no runtime allocation allowed) ----------------
__device__ float4 g_feats[NPIX];        // (resi.x, resi.y, resi.z, dist) per pixel
__device__ float  g_grp[NPIX*3];        // gathered neighbor coords per pixel
__device__ float  g_w0f[64*4],  g_b0f[64];
__device__ float  g_w1f[64*64], g_b1f[64];
__device__ float  g_w2f[128*64],g_b2f[128];

// ---------------- fold conv bias + BN (eval) into affine weights ----------------
__global__ void fold_k(const float* __restrict__ w0, const float* __restrict__ b0,
                       const float* __restrict__ g0, const float* __restrict__ be0,
                       const float* __restrict__ m0, const float* __restrict__ v0,
                       const float* __restrict__ w1, const float* __restrict__ b1,
                       const float* __restrict__ g1, const float* __restrict__ be1,
                       const float* __restrict__ m1, const float* __restrict__ v1,
                       const float* __restrict__ w2, const float* __restrict__ b2,
                       const float* __restrict__ g2, const float* __restrict__ be2,
                       const float* __restrict__ m2, const float* __restrict__ v2)
{
    int t = threadIdx.x;  // 128 threads
    for (int c = t; c < 64; c += 128) {
        float s = g0[c] / sqrtf(v0[c] + 1e-3f);
        #pragma unroll
        for (int j = 0; j < 4; j++) g_w0f[c*4+j] = w0[c*4+j] * s;
        g_b0f[c] = (b0[c] - m0[c]) * s + be0[c];
    }
    for (int c = t; c < 64; c += 128) {
        float s = g1[c] / sqrtf(v1[c] + 1e-3f);
        for (int j = 0; j < 64; j++) g_w1f[c*64+j] = w1[c*64+j] * s;
        g_b1f[c] = (b1[c] - m1[c]) * s + be1[c];
    }
    for (int c = t; c < 128; c += 128) {
        float s = g2[c] / sqrtf(v2[c] + 1e-3f);
        for (int j = 0; j < 64; j++) g_w2f[c*64+j] = w2[c*64+j] * s;
        g_b2f[c] = (b2[c] - m2[c]) * s + be2[c];
    }
}

// ---------------- KNN: one thread per query, refs tiled in smem ----------------
#define TILE 2048

__global__ __launch_bounds__(64) void knn_k(const float* __restrict__ p1,
                                            const float* __restrict__ p2)
{
    const int tid   = threadIdx.x;
    const int b     = blockIdx.y;
    const int phase = blockIdx.z;                 // 0: refs=p1, 1: refs=p2
    const int n     = blockIdx.x * 64 + tid;

    const float* Q = p1 + b * 3 * NPTS;
    const float* R = (phase ? p2 : p1) + b * 3 * NPTS;

    const float qx = Q[n], qy = Q[NPTS + n], qz = Q[2*NPTS + n];
    const float qq = qx*qx + qy*qy + qz*qz;

    const float INF = __int_as_float(0x7f800000);
    float dl[KNN];
    int   il[KNN];
    #pragma unroll
    for (int s = 0; s < KNN; s++) { dl[s] = INF; il[s] = 0; }
    float dmax = INF;
    int   ms   = 0;

    __shared__ float4 sref[TILE];

    for (int t0 = 0; t0 < NPTS; t0 += TILE) {
        for (int i = tid; i < TILE; i += 64) {
            int r = t0 + i;
            float rx = R[r], ry = R[NPTS + r], rz = R[2*NPTS + r];
            sref[i] = make_float4(rx, ry, rz, rx*rx + ry*ry + rz*rz);
        }
        __syncthreads();

        #pragma unroll 4
        for (int i = 0; i < TILE; i++) {
            float4 rv  = sref[i];
            float dot  = fmaf(qx, rv.x, fmaf(qy, rv.y, qz * rv.z));
            float d2   = fmaf(-2.f, dot, qq + rv.w);
            if (d2 < dmax) {
                // replace current max slot, then rescan for new max (branchless slots)
                #pragma unroll
                for (int s = 0; s < KNN; s++)
                    if (s == ms) { dl[s] = d2; il[s] = t0 + i; }
                dmax = dl[0]; ms = 0;
                #pragma unroll
                for (int s = 1; s < KNN; s++)
                    if (dl[s] > dmax) { dmax = dl[s]; ms = s; }
            }
        }
        __syncthreads();
    }

    // emit features + gathered coords (neighbor order irrelevant: downstream is
    // permutation-invariant over the neighbor axis)
    size_t base = ((size_t)(b * NPTS + n)) * NB + phase * KNN;
    #pragma unroll
    for (int s = 0; s < KNN; s++) {
        int r = il[s];
        float rx = R[r], ry = R[NPTS + r], rz = R[2*NPTS + r];
        float dx = rx - qx, dy = ry - qy, dz = rz - qz;
        float d  = sqrtf(fmaxf(dx*dx + dy*dy + dz*dz, 1e-12f));
        g_feats[base + s] = make_float4(dx, dy, dz, d);
        g_grp[(base + s)*3 + 0] = rx;
        g_grp[(base + s)*3 + 1] = ry;
        g_grp[(base + s)*3 + 2] = rz;
    }
}

// ---------------- fused MLP + channel-max + softmax + weighted sum --------------
// thread = one (point, neighbor) pixel; lane = neighbor; warp = point
#define SMEM_FLOATS 12800   // 4096 (W1) + 8192 (W2) + 256 (W0) + 64 + 64 + 128

__global__ __launch_bounds__(128) void mlp_k(float* __restrict__ out)
{
    extern __shared__ float sm[];
    float* sW1 = sm;                    // 64*64
    float* sW2 = sm + 4096;             // 128*64
    float* sW0 = sm + 4096 + 8192;      // 64*4
    float* sb0 = sW0 + 256;
    float* sb1 = sb0 + 64;
    float* sb2 = sb1 + 64;

    const int tid = threadIdx.x;
    for (int i = tid; i < 4096; i += 128) sW1[i] = g_w1f[i];
    for (int i = tid; i < 8192; i += 128) sW2[i] = g_w2f[i];
    for (int i = tid; i < 256;  i += 128) sW0[i] = g_w0f[i];
    if (tid < 64)  { sb0[tid] = g_b0f[tid]; sb1[tid] = g_b1f[tid]; }
    if (tid < 128) { sb2[tid] = g_b2f[tid]; }
    __syncthreads();

    const int pt   = blockIdx.x * 4 + (tid >> 5);
    const int lane = tid & 31;

    float4 x = g_feats[(size_t)pt * NB + lane];

    // layer 0: 4 -> 64
    float h0[64];
    #pragma unroll
    for (int c = 0; c < 64; c++) {
        float4 w = ((const float4*)sW0)[c];
        float a = fmaf(w.x, x.x, fmaf(w.y, x.y, fmaf(w.z, x.z, fmaf(w.w, x.w, sb0[c]))));
        h0[c] = fmaxf(a, 0.f);
    }

    // layer 1: 64 -> 64
    float h1[64];
    #pragma unroll 2
    for (int c = 0; c < 64; c++) {
        const float4* wr = (const float4*)&sW1[c * 64];
        float a0 = sb1[c], a1 = 0.f, a2 = 0.f, a3 = 0.f;
        #pragma unroll
        for (int j = 0; j < 16; j++) {
            float4 w = wr[j];
            a0 = fmaf(w.x, h0[4*j+0], a0);
            a1 = fmaf(w.y, h0[4*j+1], a1);
            a2 = fmaf(w.z, h0[4*j+2], a2);
            a3 = fmaf(w.w, h0[4*j+3], a3);
        }
        h1[c] = fmaxf((a0 + a1) + (a2 + a3), 0.f);
    }

    // layer 2: 64 -> 128, keep only running channel max
    float m = -__int_as_float(0x7f800000);
    #pragma unroll 2
    for (int c = 0; c < 128; c++) {
        const float4* wr = (const float4*)&sW2[c * 64];
        float a0 = sb2[c], a1 = 0.f, a2 = 0.f, a3 = 0.f;
        #pragma unroll
        for (int j = 0; j < 16; j++) {
            float4 w = wr[j];
            a0 = fmaf(w.x, h1[4*j+0], a0);
            a1 = fmaf(w.y, h1[4*j+1], a1);
            a2 = fmaf(w.z, h1[4*j+2], a2);
            a3 = fmaf(w.w, h1[4*j+3], a3);
        }
        float v = fmaxf((a0 + a1) + (a2 + a3), 0.f);
        m = fmaxf(m, v);
    }

    // softmax over the 32 neighbors (lanes) + weighted sum of gathered coords
    float M = m;
    #pragma unroll
    for (int o = 16; o; o >>= 1) M = fmaxf(M, __shfl_xor_sync(0xffffffffu, M, o));
    float e = expf(m - M);
    float S = e;
    #pragma unroll
    for (int o = 16; o; o >>= 1) S += __shfl_xor_sync(0xffffffffu, S, o);
    float w = e / S;

    size_t gb = ((size_t)pt * NB + lane) * 3;
    float sx = w * g_grp[gb + 0];
    float sy = w * g_grp[gb + 1];
    float sz = w * g_grp[gb + 2];
    #pragma unroll
    for (int o = 16; o; o >>= 1) {
        sx += __shfl_xor_sync(0xffffffffu, sx, o);
        sy += __shfl_xor_sync(0xffffffffu, sy, o);
        sz += __shfl_xor_sync(0xffffffffu, sz, o);
    }
    if (lane == 0) {
        int b = pt >> 12;
        int n = pt & (NPTS - 1);
        out[(b*3 + 0) * NPTS + n] = sx;
        out[(b*3 + 1) * NPTS + n] = sy;
        out[(b*3 + 2) * NPTS + n] = sz;
    }
}

// ---------------- launch ----------------
extern "C" void kernel_launch(void* const* d_in, const int* in_sizes, int n_in,
                              void* d_out, int out_size)
{
    const float* p1 = (const float*)d_in[0];
    const float* p2 = (const float*)d_in[1];
    // d_in[2] = k (fixed at 16)
    const float* w0  = (const float*)d_in[3];
    const float* b0  = (const float*)d_in[4];
    const float* g0  = (const float*)d_in[5];
    const float* be0 = (const float*)d_in[6];
    const float* m0  = (const float*)d_in[7];
    const float* v0  = (const float*)d_in[8];
    const float* w1  = (const float*)d_in[9];
    const float* b1  = (const float*)d_in[10];
    const float* g1  = (const float*)d_in[11];
    const float* be1 = (const float*)d_in[12];
    const float* m1  = (const float*)d_in[13];
    const float* v1  = (const float*)d_in[14];
    const float* w2  = (const float*)d_in[15];
    const float* b2  = (const float*)d_in[16];
    const float* g2  = (const float*)d_in[17];
    const float* be2 = (const float*)d_in[18];
    const float* m2  = (const float*)d_in[19];
    const float* v2  = (const float*)d_in[20];

    cudaFuncSetAttribute(mlp_k, cudaFuncAttributeMaxDynamicSharedMemorySize,
                         SMEM_FLOATS * (int)sizeof(float));

    fold_k<<<1, 128>>>(w0, b0, g0, be0, m0, v0,
                       w1, b1, g1, be1, m1, v1,
                       w2, b2, g2, be2, m2, v2);

    knn_k<<<dim3(NPTS/64, BATCH, 2), 64>>>(p1, p2);

    mlp_k<<<BATCH*NPTS/4, 128, SMEM_FLOATS * (int)sizeof(float)>>>((float*)d_out);
}